// round 1
// baseline (speedup 1.0000x reference)
#include <cuda_runtime.h>
#include <math.h>

#define IMG_N 16
#define IMG_H 1024
#define IMG_W 1024
#define WS    11
#define OUT_H (IMG_H - WS + 1)   // 1014
#define OUT_W (IMG_W - WS + 1)   // 1014

#define OH    16                 // output rows per tile
#define OW    246                // output cols per tile
#define IWT   256                // input cols per tile (OW + WS - 1)
#define IHT   26                 // input rows per tile (OH + WS - 1)
#define PITCH 257                // smem row pitch (conflict-free)

// ---------------- device globals (scratch; no allocation allowed) ----------
__device__ unsigned g_min1u, g_max1u, g_min2u, g_max2u;
__device__ double   g_sum;
__device__ float    g_k1, g_b1, g_k2, g_b2, g_u, g_invs;

// monotonic float<->uint mapping for atomic min/max
__device__ __forceinline__ unsigned fenc(float f) {
    unsigned b = __float_as_uint(f);
    return (b & 0x80000000u) ? ~b : (b | 0x80000000u);
}
__device__ __forceinline__ float fdec(unsigned u) {
    unsigned b = (u & 0x80000000u) ? (u ^ 0x80000000u) : ~u;
    return __uint_as_float(b);
}

__global__ void init_k() {
    g_min1u = 0xFFFFFFFFu; g_max1u = 0u;
    g_min2u = 0xFFFFFFFFu; g_max2u = 0u;
    g_sum   = 0.0;
}

// ---------------- pass 1: global min/max of both images --------------------
__global__ void minmax_k(const float4* __restrict__ a,
                         const float4* __restrict__ b, int n4) {
    float mn1 =  3.4e38f, mx1 = -3.4e38f;
    float mn2 =  3.4e38f, mx2 = -3.4e38f;
    for (int i = blockIdx.x * blockDim.x + threadIdx.x; i < n4;
         i += gridDim.x * blockDim.x) {
        float4 v = a[i];
        mn1 = fminf(mn1, fminf(fminf(v.x, v.y), fminf(v.z, v.w)));
        mx1 = fmaxf(mx1, fmaxf(fmaxf(v.x, v.y), fmaxf(v.z, v.w)));
        float4 w = b[i];
        mn2 = fminf(mn2, fminf(fminf(w.x, w.y), fminf(w.z, w.w)));
        mx2 = fmaxf(mx2, fmaxf(fmaxf(w.x, w.y), fmaxf(w.z, w.w)));
    }
    #pragma unroll
    for (int o = 16; o; o >>= 1) {
        mn1 = fminf(mn1, __shfl_down_sync(0xffffffffu, mn1, o));
        mx1 = fmaxf(mx1, __shfl_down_sync(0xffffffffu, mx1, o));
        mn2 = fminf(mn2, __shfl_down_sync(0xffffffffu, mn2, o));
        mx2 = fmaxf(mx2, __shfl_down_sync(0xffffffffu, mx2, o));
    }
    __shared__ float s0[8], s1[8], s2[8], s3[8];
    int lane = threadIdx.x & 31, warp = threadIdx.x >> 5;
    if (lane == 0) { s0[warp] = mn1; s1[warp] = mx1; s2[warp] = mn2; s3[warp] = mx2; }
    __syncthreads();
    if (threadIdx.x == 0) {
        int nw = (blockDim.x + 31) >> 5;
        for (int w = 1; w < nw; w++) {
            mn1 = fminf(mn1, s0[w]); mx1 = fmaxf(mx1, s1[w]);
            mn2 = fminf(mn2, s2[w]); mx2 = fmaxf(mx2, s3[w]);
        }
        atomicMin(&g_min1u, fenc(mn1)); atomicMax(&g_max1u, fenc(mx1));
        atomicMin(&g_min2u, fenc(mn2)); atomicMax(&g_max2u, fenc(mx2));
    }
}

// ---------------- pass 2: derive normalization + TMQI constants ------------
__global__ void prep_k() {
    float mn1 = fdec(g_min1u), mx1 = fdec(g_max1u);
    float mn2 = fdec(g_min2u), mx2 = fdec(g_max2u);
    float k1 = 255.0f / (mx1 - mn1 + 1e-6f);
    float k2 = 255.0f / (mx2 - mn2 + 1e-6f);
    g_k1 = k1; g_b1 = -mn1 * k1;
    g_k2 = k2; g_b2 = -mn2 * k2;
    double csf = 100.0 * 2.6 * (0.0192 + 0.114 * 16.0) * exp(-pow(0.114 * 16.0, 1.1));
    double u   = 128.0 / (1.4 * csf);
    double sg  = u / 3.0;
    g_u    = (float)u;
    g_invs = (float)(1.0 / (sg * sqrt(2.0)));
}

// ---------------- pass 3: fused box-filter + TMQI map + reduction ----------
__global__ __launch_bounds__(256, 2)
void tmqi_k(const float* __restrict__ img1, const float* __restrict__ img2) {
    extern __shared__ float vs[];      // 5 * OH * PITCH floats = 82240 B
    const int tid = threadIdx.x;
    const int ox0 = blockIdx.x * OW;
    const int oy0 = blockIdx.y * OH;
    const int bz  = blockIdx.z;
    const int gx  = ox0 + tid;

    const float k1 = g_k1, b1 = g_b1, k2 = g_k2, b2 = g_b2;
    const float* p1 = img1 + (size_t)bz * IMG_H * IMG_W;
    const float* p2 = img2 + (size_t)bz * IMG_H * IMG_W;

    // --- phase 1: per-column load + normalize + vertical sliding sums ---
    float a1[IHT], a2[IHT];
    const bool colok = (gx < IMG_W);
    #pragma unroll
    for (int r = 0; r < IHT; r++) {
        int gr = oy0 + r;
        bool ok = colok && (gr < IMG_H);
        float v1 = ok ? __ldg(p1 + gr * IMG_W + gx) : 0.0f;
        float v2 = ok ? __ldg(p2 + gr * IMG_W + gx) : 0.0f;
        a1[r] = fmaf(v1, k1, b1);
        a2[r] = fmaf(v2, k2, b2);
    }
    float s1 = 0.f, s2 = 0.f, s11 = 0.f, s22 = 0.f, s12 = 0.f;
    #pragma unroll
    for (int r = 0; r < IHT; r++) {
        float x1 = a1[r], x2 = a2[r];
        s1 += x1; s2 += x2;
        s11 = fmaf(x1, x1, s11);
        s22 = fmaf(x2, x2, s22);
        s12 = fmaf(x1, x2, s12);
        if (r >= WS - 1) {
            int orow = r - (WS - 1);
            vs[(0 * OH + orow) * PITCH + tid] = s1;
            vs[(1 * OH + orow) * PITCH + tid] = s2;
            vs[(2 * OH + orow) * PITCH + tid] = s11;
            vs[(3 * OH + orow) * PITCH + tid] = s22;
            vs[(4 * OH + orow) * PITCH + tid] = s12;
            float o1 = a1[orow], o2 = a2[orow];
            s1 -= o1; s2 -= o2;
            s11 -= o1 * o1; s22 -= o2 * o2; s12 -= o1 * o2;
        }
    }
    __syncthreads();

    // --- phase 2: horizontal sliding sums + TMQI map ---
    float acc = 0.0f;
    const int r     = tid & 15;
    const int chunk = tid >> 4;
    const int x0    = chunk * 16;
    const int goy   = oy0 + r;
    if (goy < OUT_H) {
        const int cnt = min(16, OW - x0);      // last chunk handles 6
        const int q0 = (0 * OH + r) * PITCH + x0;
        const int q1 = (1 * OH + r) * PITCH + x0;
        const int q2 = (2 * OH + r) * PITCH + x0;
        const int q3 = (3 * OH + r) * PITCH + x0;
        const int q4 = (4 * OH + r) * PITCH + x0;
        float h0 = 0.f, h1 = 0.f, h2 = 0.f, h3 = 0.f, h4 = 0.f;
        #pragma unroll
        for (int j = 0; j < WS - 1; j++) {
            h0 += vs[q0 + j]; h1 += vs[q1 + j]; h2 += vs[q2 + j];
            h3 += vs[q3 + j]; h4 += vs[q4 + j];
        }
        const float U = g_u, IS = g_invs;
        const float w = 1.0f / (float)(WS * WS);
        for (int i = 0; i < cnt; i++) {
            h0 += vs[q0 + i + WS - 1]; h1 += vs[q1 + i + WS - 1];
            h2 += vs[q2 + i + WS - 1]; h3 += vs[q3 + i + WS - 1];
            h4 += vs[q4 + i + WS - 1];
            int gox = ox0 + x0 + i;
            if (gox < OUT_W) {
                float mu1 = h0 * w, mu2 = h1 * w;
                float v1 = h2 * w - mu1 * mu1;
                float v2 = h3 * w - mu2 * mu2;
                float cv = h4 * w - mu1 * mu2;
                float sg1 = sqrtf(fmaxf(v1, 0.0f) + 1e-6f);
                float sg2 = sqrtf(fmaxf(v2, 0.0f) + 1e-6f);
                float pA = 0.5f * (1.0f + erff((sg1 - U) * IS));
                float pB = 0.5f * (1.0f + erff((sg2 - U) * IS));
                float num = 2.0f * pA * pB + 0.01f;
                float den = pA * pA + pB * pB + 0.01f;
                float str = (cv + 10.0f) / (sg1 * sg2 + 10.0f);
                acc += (num / den) * str;
            }
            h0 -= vs[q0 + i]; h1 -= vs[q1 + i]; h2 -= vs[q2 + i];
            h3 -= vs[q3 + i]; h4 -= vs[q4 + i];
        }
    }

    // --- block reduction ---
    #pragma unroll
    for (int o = 16; o; o >>= 1)
        acc += __shfl_down_sync(0xffffffffu, acc, o);
    __shared__ float red[8];
    if ((tid & 31) == 0) red[tid >> 5] = acc;
    __syncthreads();
    if (tid == 0) {
        float v = red[0];
        #pragma unroll
        for (int i = 1; i < 8; i++) v += red[i];
        atomicAdd(&g_sum, (double)v);
    }
}

__global__ void final_k(float* out) {
    out[0] = (float)(g_sum / ((double)IMG_N * OUT_H * OUT_W));
}

// ---------------- launch ----------------------------------------------------
extern "C" void kernel_launch(void* const* d_in, const int* in_sizes, int n_in,
                              void* d_out, int out_size) {
    const float* img1 = (const float*)d_in[0];
    const float* img2 = (const float*)d_in[1];
    float* out = (float*)d_out;

    init_k<<<1, 1>>>();

    int n4 = (IMG_N * IMG_H * IMG_W) / 4;
    minmax_k<<<2048, 256>>>((const float4*)img1, (const float4*)img2, n4);

    prep_k<<<1, 1>>>();

    size_t smem = (size_t)5 * OH * PITCH * sizeof(float);   // 82240 B
    cudaFuncSetAttribute(tmqi_k, cudaFuncAttributeMaxDynamicSharedMemorySize,
                         (int)smem);
    dim3 grid((OUT_W + OW - 1) / OW, (OUT_H + OH - 1) / OH, IMG_N);  // (5,64,16)
    tmqi_k<<<grid, 256, smem>>>(img1, img2);

    final_k<<<1, 1>>>(out);
}

// round 3
// speedup vs baseline: 1.4232x; 1.4232x over previous
#include <cuda_runtime.h>
#include <math.h>

#define IMG_N 16
#define IMG_H 1024
#define IMG_W 1024
#define WS    11
#define OUT_H (IMG_H - WS + 1)   // 1014
#define OUT_W (IMG_W - WS + 1)   // 1014

#define OH    16                 // output rows per tile
#define OW    240                // output cols per tile (16 chunks x 15)
#define CHW   15                 // outputs per thread in phase 2
#define IHT   26                 // input rows per tile (OH + WS - 1)
#define PITCH 257                // smem row pitch (>= 256 writers!)
#define GX    5                  // ceil(1014/240)
#define GY    64                 // ceil(1014/16)

// ---------------- device globals ----------
__device__ unsigned g_min1u, g_max1u, g_min2u, g_max2u;
__device__ double   g_sum;
__device__ float    g_k1, g_b1, g_k2, g_b2, g_u, g_invs, g_thr;

__device__ __forceinline__ unsigned fenc(float f) {
    unsigned b = __float_as_uint(f);
    return (b & 0x80000000u) ? ~b : (b | 0x80000000u);
}
__device__ __forceinline__ float fdec(unsigned u) {
    unsigned b = (u & 0x80000000u) ? (u ^ 0x80000000u) : ~u;
    return __uint_as_float(b);
}

__global__ void init_k() {
    g_min1u = 0xFFFFFFFFu; g_max1u = 0u;
    g_min2u = 0xFFFFFFFFu; g_max2u = 0u;
    g_sum   = 0.0;
}

// ---------------- pass 1: global min/max --------------------
__global__ void minmax_k(const float4* __restrict__ a,
                         const float4* __restrict__ b, int n4) {
    float mn1 =  3.4e38f, mx1 = -3.4e38f;
    float mn2 =  3.4e38f, mx2 = -3.4e38f;
    for (int i = blockIdx.x * blockDim.x + threadIdx.x; i < n4;
         i += gridDim.x * blockDim.x) {
        float4 v = a[i];
        mn1 = fminf(mn1, fminf(fminf(v.x, v.y), fminf(v.z, v.w)));
        mx1 = fmaxf(mx1, fmaxf(fmaxf(v.x, v.y), fmaxf(v.z, v.w)));
        float4 w = b[i];
        mn2 = fminf(mn2, fminf(fminf(w.x, w.y), fminf(w.z, w.w)));
        mx2 = fmaxf(mx2, fmaxf(fmaxf(w.x, w.y), fmaxf(w.z, w.w)));
    }
    #pragma unroll
    for (int o = 16; o; o >>= 1) {
        mn1 = fminf(mn1, __shfl_down_sync(0xffffffffu, mn1, o));
        mx1 = fmaxf(mx1, __shfl_down_sync(0xffffffffu, mx1, o));
        mn2 = fminf(mn2, __shfl_down_sync(0xffffffffu, mn2, o));
        mx2 = fmaxf(mx2, __shfl_down_sync(0xffffffffu, mx2, o));
    }
    __shared__ float s0[8], s1[8], s2[8], s3[8];
    int lane = threadIdx.x & 31, warp = threadIdx.x >> 5;
    if (lane == 0) { s0[warp] = mn1; s1[warp] = mx1; s2[warp] = mn2; s3[warp] = mx2; }
    __syncthreads();
    if (threadIdx.x == 0) {
        for (int w = 1; w < 8; w++) {
            mn1 = fminf(mn1, s0[w]); mx1 = fmaxf(mx1, s1[w]);
            mn2 = fminf(mn2, s2[w]); mx2 = fmaxf(mx2, s3[w]);
        }
        atomicMin(&g_min1u, fenc(mn1)); atomicMax(&g_max1u, fenc(mx1));
        atomicMin(&g_min2u, fenc(mn2)); atomicMax(&g_max2u, fenc(mx2));
    }
}

// ---------------- pass 2: constants ------------
__global__ void prep_k() {
    float mn1 = fdec(g_min1u), mx1 = fdec(g_max1u);
    float mn2 = fdec(g_min2u), mx2 = fdec(g_max2u);
    float k1 = 255.0f / (mx1 - mn1 + 1e-6f);
    float k2 = 255.0f / (mx2 - mn2 + 1e-6f);
    g_k1 = k1; g_b1 = -mn1 * k1;
    g_k2 = k2; g_b2 = -mn2 * k2;
    double csf = 100.0 * 2.6 * (0.0192 + 0.114 * 16.0) * exp(-pow(0.114 * 16.0, 1.1));
    double u   = 128.0 / (1.4 * csf);
    double sg  = u / 3.0;
    g_u    = (float)u;
    g_invs = (float)(1.0 / (sg * sqrt(2.0)));
    // variance threshold: erf arg >= 4  =>  sigma >= u + 4*sg*sqrt(2)
    double st = u + 4.0 * sg * sqrt(2.0);
    g_thr = (float)(st * st);
}

// exact slow path (kept out of the hot loop; warp-uniform, rarely taken)
__device__ __noinline__ float slow_px(float v1, float v2, float cv,
                                      float U, float IS) {
    float sg1 = sqrtf(fmaxf(v1, 0.0f) + 1e-6f);
    float sg2 = sqrtf(fmaxf(v2, 0.0f) + 1e-6f);
    float pA = 0.5f * (1.0f + erff((sg1 - U) * IS));
    float pB = 0.5f * (1.0f + erff((sg2 - U) * IS));
    float num = 2.0f * pA * pB + 0.01f;
    float den = pA * pA + pB * pB + 0.01f;
    return (num / den) * ((cv + 10.0f) / (sg1 * sg2 + 10.0f));
}

__device__ __forceinline__ float px_val(float h0, float h1, float h2,
                                        float h3, float h4,
                                        float thr, float U, float IS) {
    float m1 = h0, m2 = h1;
    float v1 = fmaf(-m1, m1, h2);
    float v2 = fmaf(-m2, m2, h3);
    float cv = fmaf(-m1, m2, h4);
    float vmin = fminf(v1, v2);
    if (vmin > thr) {
        // luminance ratio is exactly 1 (erf saturates to 1.0f in fp32)
        float p = (v1 + 1e-6f) * (v2 + 1e-6f);
        float s = p * rsqrtf(p);                 // = sg1*sg2
        return __fdividef(cv + 10.0f, s + 10.0f);
    }
    return slow_px(v1, v2, cv, U, IS);
}

// ---------------- pass 3: fused box-filter + TMQI + reduction ----------
__global__ __launch_bounds__(256, 2)
void tmqi_k(const float* __restrict__ img1, const float* __restrict__ img2) {
    extern __shared__ float vs[];      // 5 * OH * PITCH floats = 82240 B
    const int tid = threadIdx.x;
    const int ox0 = blockIdx.x * OW;
    const int oy0 = blockIdx.y * OH;
    const int bz  = blockIdx.z;
    const int gx  = ox0 + tid;
    const bool full = (blockIdx.x < GX - 1) && (blockIdx.y < GY - 1);

    const float k1 = g_k1, b1 = g_b1, k2 = g_k2, b2 = g_b2;
    const float w = 1.0f / (float)(WS * WS);
    const float* p1 = img1 + (size_t)bz * IMG_H * IMG_W + (size_t)oy0 * IMG_W + gx;
    const float* p2 = img2 + (size_t)bz * IMG_H * IMG_W + (size_t)oy0 * IMG_W + gx;

    // --- phase 1: load + normalize + vertical sliding sums ---
    float a1[IHT], a2[IHT];
    if (full) {
        #pragma unroll
        for (int r = 0; r < IHT; r++) {
            a1[r] = fmaf(__ldg(p1 + r * IMG_W), k1, b1);
            a2[r] = fmaf(__ldg(p2 + r * IMG_W), k2, b2);
        }
    } else {
        const bool colok = (gx < IMG_W);
        #pragma unroll
        for (int r = 0; r < IHT; r++) {
            bool ok = colok && (oy0 + r < IMG_H);
            float v1 = ok ? __ldg(p1 + r * IMG_W) : 0.0f;
            float v2 = ok ? __ldg(p2 + r * IMG_W) : 0.0f;
            a1[r] = fmaf(v1, k1, b1);
            a2[r] = fmaf(v2, k2, b2);
        }
    }
    {
        float s1 = 0.f, s2 = 0.f, s11 = 0.f, s22 = 0.f, s12 = 0.f;
        #pragma unroll
        for (int r = 0; r < IHT; r++) {
            float x1 = a1[r], x2 = a2[r];
            s1 += x1; s2 += x2;
            s11 = fmaf(x1, x1, s11);
            s22 = fmaf(x2, x2, s22);
            s12 = fmaf(x1, x2, s12);
            if (r >= WS - 1) {
                int orow = r - (WS - 1);
                vs[(0 * OH + orow) * PITCH + tid] = s1  * w;
                vs[(1 * OH + orow) * PITCH + tid] = s2  * w;
                vs[(2 * OH + orow) * PITCH + tid] = s11 * w;
                vs[(3 * OH + orow) * PITCH + tid] = s22 * w;
                vs[(4 * OH + orow) * PITCH + tid] = s12 * w;
                float o1 = a1[orow], o2 = a2[orow];
                s1 -= o1; s2 -= o2;
                s11 -= o1 * o1; s22 -= o2 * o2; s12 -= o1 * o2;
            }
        }
    }
    __syncthreads();

    // --- phase 2: horizontal sliding sums + TMQI map ---
    float acc = 0.0f;
    {
        const int r     = tid & 15;
        const int x0    = (tid >> 4) * CHW;
        const int q0 = (0 * OH + r) * PITCH + x0;
        const int q1 = (1 * OH + r) * PITCH + x0;
        const int q2 = (2 * OH + r) * PITCH + x0;
        const int q3 = (3 * OH + r) * PITCH + x0;
        const int q4 = (4 * OH + r) * PITCH + x0;
        const float U = g_u, IS = g_invs, thr = g_thr;

        if (full) {
            float h0 = 0.f, h1 = 0.f, h2 = 0.f, h3 = 0.f, h4 = 0.f;
            #pragma unroll
            for (int j = 0; j < WS - 1; j++) {
                h0 += vs[q0 + j]; h1 += vs[q1 + j]; h2 += vs[q2 + j];
                h3 += vs[q3 + j]; h4 += vs[q4 + j];
            }
            #pragma unroll
            for (int i = 0; i < CHW; i++) {
                h0 += vs[q0 + i + WS - 1]; h1 += vs[q1 + i + WS - 1];
                h2 += vs[q2 + i + WS - 1]; h3 += vs[q3 + i + WS - 1];
                h4 += vs[q4 + i + WS - 1];
                acc += px_val(h0, h1, h2, h3, h4, thr, U, IS);
                h0 -= vs[q0 + i]; h1 -= vs[q1 + i]; h2 -= vs[q2 + i];
                h3 -= vs[q3 + i]; h4 -= vs[q4 + i];
            }
        } else if (oy0 + r < OUT_H) {
            float h0 = 0.f, h1 = 0.f, h2 = 0.f, h3 = 0.f, h4 = 0.f;
            #pragma unroll
            for (int j = 0; j < WS - 1; j++) {
                h0 += vs[q0 + j]; h1 += vs[q1 + j]; h2 += vs[q2 + j];
                h3 += vs[q3 + j]; h4 += vs[q4 + j];
            }
            for (int i = 0; i < CHW; i++) {
                h0 += vs[q0 + i + WS - 1]; h1 += vs[q1 + i + WS - 1];
                h2 += vs[q2 + i + WS - 1]; h3 += vs[q3 + i + WS - 1];
                h4 += vs[q4 + i + WS - 1];
                if (ox0 + x0 + i < OUT_W)
                    acc += px_val(h0, h1, h2, h3, h4, thr, U, IS);
                h0 -= vs[q0 + i]; h1 -= vs[q1 + i]; h2 -= vs[q2 + i];
                h3 -= vs[q3 + i]; h4 -= vs[q4 + i];
            }
        }
    }

    // --- block reduction ---
    #pragma unroll
    for (int o = 16; o; o >>= 1)
        acc += __shfl_down_sync(0xffffffffu, acc, o);
    __shared__ float red[8];
    if ((tid & 31) == 0) red[tid >> 5] = acc;
    __syncthreads();
    if (tid == 0) {
        float v = red[0];
        #pragma unroll
        for (int i = 1; i < 8; i++) v += red[i];
        atomicAdd(&g_sum, (double)v);
    }
}

__global__ void final_k(float* out) {
    out[0] = (float)(g_sum / ((double)IMG_N * OUT_H * OUT_W));
}

// ---------------- launch -----------------------------------------------
extern "C" void kernel_launch(void* const* d_in, const int* in_sizes, int n_in,
                              void* d_out, int out_size) {
    const float* img1 = (const float*)d_in[0];
    const float* img2 = (const float*)d_in[1];
    float* out = (float*)d_out;

    init_k<<<1, 1>>>();

    int n4 = (IMG_N * IMG_H * IMG_W) / 4;
    minmax_k<<<2048, 256>>>((const float4*)img1, (const float4*)img2, n4);

    prep_k<<<1, 1>>>();

    size_t smem = (size_t)5 * OH * PITCH * sizeof(float);   // 82240 B
    cudaFuncSetAttribute(tmqi_k, cudaFuncAttributeMaxDynamicSharedMemorySize,
                         (int)smem);
    dim3 grid(GX, GY, IMG_N);   // (5, 64, 16)
    tmqi_k<<<grid, 256, smem>>>(img1, img2);

    final_k<<<1, 1>>>(out);
}

// round 4
// speedup vs baseline: 1.5425x; 1.0838x over previous
#include <cuda_runtime.h>
#include <math.h>

#define IMG_N 16
#define IMG_H 1024
#define IMG_W 1024
#define WS    11
#define OUT_H (IMG_H - WS + 1)   // 1014
#define OUT_W (IMG_W - WS + 1)   // 1014

#define OH    16                 // output rows per tile
#define OWT   256                // output cols per tile (16 chunks x 16)
#define ICT   266                // input cols per tile (OWT + WS - 1)
#define IHT   26                 // input rows per tile (OH + WS - 1)
#define PA    274                // pitch of pair buffers (float2 units)  (274*2 % 32 == 4)
#define PC    292                // pitch of scalar buffer (floats)       (292 % 32 == 4)
#define GX    4                  // ceil(1014/256)
#define GY    64                 // ceil(1014/16)

#define A_BYTES (OH * PA * 8)            // 35072
#define B_OFF   A_BYTES                  // 35072
#define C_OFF   (2 * A_BYTES)            // 70144
#define SMEM_BYTES (C_OFF + OH * PC * 4) // 88832

// ---------------- packed f32x2 helpers ----------------
__device__ __forceinline__ unsigned long long f2add(unsigned long long a,
                                                    unsigned long long b) {
    unsigned long long r;
    asm("add.rn.f32x2 %0, %1, %2;" : "=l"(r) : "l"(a), "l"(b));
    return r;
}
__device__ __forceinline__ unsigned long long f2fma(unsigned long long a,
                                                    unsigned long long b,
                                                    unsigned long long c) {
    unsigned long long r;
    asm("fma.rn.f32x2 %0, %1, %2, %3;" : "=l"(r) : "l"(a), "l"(b), "l"(c));
    return r;
}
__device__ __forceinline__ void f2unpack(unsigned long long v, float& lo, float& hi) {
    asm("mov.b64 {%0, %1}, %2;" : "=f"(lo), "=f"(hi) : "l"(v));
}
#define F2_NEG1 0xBF800000BF800000ULL
#define F2_SGN  0x8000000080000000ULL

// ---------------- device globals ----------
__device__ unsigned g_min1u, g_max1u, g_min2u, g_max2u;
__device__ double   g_sum;
__device__ float    g_k1, g_b1, g_k2, g_b2, g_u, g_invs, g_thr;

__device__ __forceinline__ unsigned fenc(float f) {
    unsigned b = __float_as_uint(f);
    return (b & 0x80000000u) ? ~b : (b | 0x80000000u);
}
__device__ __forceinline__ float fdec(unsigned u) {
    unsigned b = (u & 0x80000000u) ? (u ^ 0x80000000u) : ~u;
    return __uint_as_float(b);
}

__global__ void init_k() {
    g_min1u = 0xFFFFFFFFu; g_max1u = 0u;
    g_min2u = 0xFFFFFFFFu; g_max2u = 0u;
    g_sum   = 0.0;
}

// ---------------- pass 1: global min/max --------------------
__global__ void minmax_k(const float4* __restrict__ a,
                         const float4* __restrict__ b, int n4) {
    float mn1 =  3.4e38f, mx1 = -3.4e38f;
    float mn2 =  3.4e38f, mx2 = -3.4e38f;
    for (int i = blockIdx.x * blockDim.x + threadIdx.x; i < n4;
         i += gridDim.x * blockDim.x) {
        float4 v = a[i];
        mn1 = fminf(mn1, fminf(fminf(v.x, v.y), fminf(v.z, v.w)));
        mx1 = fmaxf(mx1, fmaxf(fmaxf(v.x, v.y), fmaxf(v.z, v.w)));
        float4 w = b[i];
        mn2 = fminf(mn2, fminf(fminf(w.x, w.y), fminf(w.z, w.w)));
        mx2 = fmaxf(mx2, fmaxf(fmaxf(w.x, w.y), fmaxf(w.z, w.w)));
    }
    #pragma unroll
    for (int o = 16; o; o >>= 1) {
        mn1 = fminf(mn1, __shfl_down_sync(0xffffffffu, mn1, o));
        mx1 = fmaxf(mx1, __shfl_down_sync(0xffffffffu, mx1, o));
        mn2 = fminf(mn2, __shfl_down_sync(0xffffffffu, mn2, o));
        mx2 = fmaxf(mx2, __shfl_down_sync(0xffffffffu, mx2, o));
    }
    __shared__ float s0[8], s1[8], s2[8], s3[8];
    int lane = threadIdx.x & 31, warp = threadIdx.x >> 5;
    if (lane == 0) { s0[warp] = mn1; s1[warp] = mx1; s2[warp] = mn2; s3[warp] = mx2; }
    __syncthreads();
    if (threadIdx.x == 0) {
        for (int w = 1; w < 8; w++) {
            mn1 = fminf(mn1, s0[w]); mx1 = fmaxf(mx1, s1[w]);
            mn2 = fminf(mn2, s2[w]); mx2 = fmaxf(mx2, s3[w]);
        }
        atomicMin(&g_min1u, fenc(mn1)); atomicMax(&g_max1u, fenc(mx1));
        atomicMin(&g_min2u, fenc(mn2)); atomicMax(&g_max2u, fenc(mx2));
    }
}

// ---------------- pass 2: constants ------------
__global__ void prep_k() {
    float mn1 = fdec(g_min1u), mx1 = fdec(g_max1u);
    float mn2 = fdec(g_min2u), mx2 = fdec(g_max2u);
    float k1 = 255.0f / (mx1 - mn1 + 1e-6f);
    float k2 = 255.0f / (mx2 - mn2 + 1e-6f);
    g_k1 = k1; g_b1 = -mn1 * k1;
    g_k2 = k2; g_b2 = -mn2 * k2;
    double csf = 100.0 * 2.6 * (0.0192 + 0.114 * 16.0) * exp(-pow(0.114 * 16.0, 1.1));
    double u   = 128.0 / (1.4 * csf);
    double sg  = u / 3.0;
    g_u    = (float)u;
    g_invs = (float)(1.0 / (sg * sqrt(2.0)));
    double st = u + 4.0 * sg * sqrt(2.0);   // erf arg >= 4 => saturates to 1.0f
    g_thr = (float)(st * st);
}

// exact slow path (out of hot loop; warp-uniform, never taken on this data)
__device__ __noinline__ float slow_px(float v1, float v2, float cv,
                                      float U, float IS) {
    float sg1 = sqrtf(fmaxf(v1, 0.0f) + 1e-6f);
    float sg2 = sqrtf(fmaxf(v2, 0.0f) + 1e-6f);
    float pA = 0.5f * (1.0f + erff((sg1 - U) * IS));
    float pB = 0.5f * (1.0f + erff((sg2 - U) * IS));
    float num = 2.0f * pA * pB + 0.01f;
    float den = pA * pA + pB * pB + 0.01f;
    return (num / den) * ((cv + 10.0f) / (sg1 * sg2 + 10.0f));
}

__device__ __forceinline__ float px_val(float v1, float v2, float cv,
                                        float thr, float U, float IS) {
    if (fminf(v1, v2) > thr) {
        float p = (v1 + 1e-6f) * (v2 + 1e-6f);
        float s = p * rsqrtf(p);                 // = sg1*sg2
        return __fdividef(cv + 10.0f, s + 10.0f);
    }
    return slow_px(v1, v2, cv, U, IS);
}

// ---------------- phase 1 vertical pass for one column ----------------
template<bool GUARD>
__device__ __forceinline__ void vcol(const float* __restrict__ q1,
                                     const float* __restrict__ q2,
                                     int rowlim, bool colok,
                                     float k1, float b1, float k2, float b2,
                                     float wgt,
                                     float2* __restrict__ Ac,
                                     float2* __restrict__ Bc,
                                     float*  __restrict__ Cc) {
    float a1[IHT], a2[IHT];
    #pragma unroll
    for (int rr = 0; rr < IHT; rr++) {
        float v1, v2;
        if (GUARD) {
            bool ok = colok && (rr < rowlim);
            v1 = ok ? __ldg(q1 + rr * IMG_W) : 0.0f;
            v2 = ok ? __ldg(q2 + rr * IMG_W) : 0.0f;
        } else {
            v1 = __ldg(q1 + rr * IMG_W);
            v2 = __ldg(q2 + rr * IMG_W);
        }
        a1[rr] = fmaf(v1, k1, b1);
        a2[rr] = fmaf(v2, k2, b2);
    }
    float s1 = 0.f, s2 = 0.f, s11 = 0.f, s22 = 0.f, s12 = 0.f;
    #pragma unroll
    for (int rr = 0; rr < IHT; rr++) {
        float x1 = a1[rr], x2 = a2[rr];
        s1 += x1; s2 += x2;
        s11 = fmaf(x1, x1, s11);
        s22 = fmaf(x2, x2, s22);
        s12 = fmaf(x1, x2, s12);
        if (rr >= WS - 1) {
            int o = rr - (WS - 1);
            Ac[o * PA] = make_float2(s1 * wgt, s2 * wgt);
            Bc[o * PA] = make_float2(s11 * wgt, s22 * wgt);
            Cc[o * PC] = s12 * wgt;
            float o1 = a1[o], o2 = a2[o];
            s1 -= o1; s2 -= o2;
            s11 -= o1 * o1; s22 -= o2 * o2; s12 -= o1 * o2;
        }
    }
}

// ---------------- pass 3: fused box-filter + TMQI + reduction ----------
__global__ __launch_bounds__(256, 2)
void tmqi_k(const float* __restrict__ img1, const float* __restrict__ img2) {
    extern __shared__ char sm[];
    float2* A = (float2*)sm;
    float2* B = (float2*)(sm + B_OFF);
    float*  C = (float*)(sm + C_OFF);

    const int tid = threadIdx.x;
    const int ox0 = blockIdx.x * OWT;
    const int oy0 = blockIdx.y * OH;
    const int bz  = blockIdx.z;
    const bool full = (blockIdx.x < GX - 1) && (blockIdx.y < GY - 1);

    const float k1 = g_k1, b1 = g_b1, k2 = g_k2, b2 = g_b2;
    const float wgt = 1.0f / (float)(WS * WS);
    const float* p1 = img1 + (size_t)bz * IMG_H * IMG_W + (size_t)oy0 * IMG_W + ox0;
    const float* p2 = img2 + (size_t)bz * IMG_H * IMG_W + (size_t)oy0 * IMG_W + ox0;
    const int rowlim = min(IHT, IMG_H - oy0);

    // --- phase 1: main column (always in-range horizontally) ---
    if (full)
        vcol<false>(p1 + tid, p2 + tid, IHT, true, k1, b1, k2, b2, wgt,
                    A + tid, B + tid, C + tid);
    else
        vcol<true>(p1 + tid, p2 + tid, rowlim, true, k1, b1, k2, b2, wgt,
                   A + tid, B + tid, C + tid);
    // --- phase 1: halo columns 256..265 handled by threads 0..9 ---
    if (tid < ICT - 256) {
        int col = 256 + tid;
        if (full)
            vcol<false>(p1 + col, p2 + col, IHT, true, k1, b1, k2, b2, wgt,
                        A + col, B + col, C + col);
        else {
            bool ok = (ox0 + col < IMG_W);
            vcol<true>(p1 + col, p2 + col, rowlim, ok, k1, b1, k2, b2, wgt,
                       A + col, B + col, C + col);
        }
    }
    __syncthreads();

    // --- phase 2: horizontal windows in registers + TMQI map ---
    float acc = 0.0f;
    {
        const int r  = tid & 15;
        const int ck = tid >> 4;
        const int x0 = ck * 16;
        const float U = g_u, IS = g_invs, thr = g_thr;
        const bool rowok = full || (oy0 + r < OUT_H);
        const int maxi = OUT_W - (ox0 + x0);   // valid outputs: i < maxi

        // ---- channel s12 (scalar): 28 values, slide -> cvw[16]
        float cvw[16];
        {
            float bufc[28];
            const float4* Cs = (const float4*)(C + r * PC + x0);
            #pragma unroll
            for (int j = 0; j < 7; j++) *(float4*)&bufc[4 * j] = Cs[j];
            float h = bufc[0];
            #pragma unroll
            for (int j = 1; j < WS; j++) h += bufc[j];
            cvw[0] = h;
            #pragma unroll
            for (int i = 1; i < 16; i++) {
                h += bufc[i + WS - 1] - bufc[i - 1];
                cvw[i] = h;
            }
        }

        unsigned long long pa[26];

        // ---- channel pair (s11,s22): packed slide -> sw[16]
        unsigned long long sw[16];
        {
            const ulonglong2* Bs = (const ulonglong2*)(B + r * PA + x0);
            #pragma unroll
            for (int j = 0; j < 13; j++) {
                ulonglong2 t = Bs[j];
                pa[2 * j] = t.x; pa[2 * j + 1] = t.y;
            }
            unsigned long long h = pa[0];
            #pragma unroll
            for (int j = 1; j < WS; j++) h = f2add(h, pa[j]);
            sw[0] = h;
            #pragma unroll
            for (int i = 1; i < 16; i++) {
                h = f2add(h, pa[i + WS - 1]);
                h = f2fma(pa[i - 1], F2_NEG1, h);
                sw[i] = h;
            }
        }

        // ---- channel pair (s1,s2): packed slide fused with per-pixel math
        {
            const ulonglong2* As = (const ulonglong2*)(A + r * PA + x0);
            #pragma unroll
            for (int j = 0; j < 13; j++) {
                ulonglong2 t = As[j];
                pa[2 * j] = t.x; pa[2 * j + 1] = t.y;
            }
            unsigned long long h = pa[0];
            #pragma unroll
            for (int j = 1; j < WS; j++) h = f2add(h, pa[j]);
            #pragma unroll
            for (int i = 0; i < 16; i++) {
                if (i) {
                    h = f2add(h, pa[i + WS - 1]);
                    h = f2fma(pa[i - 1], F2_NEG1, h);
                }
                unsigned long long m12 = h;
                unsigned long long v12 = f2fma(m12, m12 ^ F2_SGN, sw[i]); // s - m*m
                float m1, m2, v1, v2;
                f2unpack(m12, m1, m2);
                f2unpack(v12, v1, v2);
                float cv = fmaf(-m1, m2, cvw[i]);
                if (rowok && i < maxi)
                    acc += px_val(v1, v2, cv, thr, U, IS);
            }
        }
    }

    // --- block reduction ---
    #pragma unroll
    for (int o = 16; o; o >>= 1)
        acc += __shfl_down_sync(0xffffffffu, acc, o);
    __shared__ float red[8];
    if ((tid & 31) == 0) red[tid >> 5] = acc;
    __syncthreads();
    if (tid == 0) {
        float v = red[0];
        #pragma unroll
        for (int i = 1; i < 8; i++) v += red[i];
        atomicAdd(&g_sum, (double)v);
    }
}

__global__ void final_k(float* out) {
    out[0] = (float)(g_sum / ((double)IMG_N * OUT_H * OUT_W));
}

// ---------------- launch -----------------------------------------------
extern "C" void kernel_launch(void* const* d_in, const int* in_sizes, int n_in,
                              void* d_out, int out_size) {
    const float* img1 = (const float*)d_in[0];
    const float* img2 = (const float*)d_in[1];
    float* out = (float*)d_out;

    init_k<<<1, 1>>>();

    int n4 = (IMG_N * IMG_H * IMG_W) / 4;
    minmax_k<<<2048, 256>>>((const float4*)img1, (const float4*)img2, n4);

    prep_k<<<1, 1>>>();

    cudaFuncSetAttribute(tmqi_k, cudaFuncAttributeMaxDynamicSharedMemorySize,
                         SMEM_BYTES);
    dim3 grid(GX, GY, IMG_N);   // (4, 64, 16)
    tmqi_k<<<grid, 256, SMEM_BYTES>>>(img1, img2);

    final_k<<<1, 1>>>(out);
}

// round 5
// speedup vs baseline: 1.5617x; 1.0125x over previous
#include <cuda_runtime.h>
#include <math.h>

#define IMG_N 16
#define IMG_H 1024
#define IMG_W 1024
#define WS    11
#define OUT_H (IMG_H - WS + 1)   // 1014
#define OUT_W (IMG_W - WS + 1)   // 1014

#define NTHR  288                // 9 warps
#define OH    16                 // output rows per tile
#define NCK   18                 // chunks (NTHR/OH)
#define CW    15                 // outputs per thread
#define OWT   (NCK * CW)         // 270 output cols per tile
#define ICT   (OWT + WS - 1)     // 280 input cols per tile
#define IHT   (OH + WS - 1)      // 26 input rows per tile
#define PAB   281                // float4 pitch (odd -> LDS.128 conflict-free)
#define PC    290                // float pitch (== 2 mod 32 -> conflict-free)
#define GX    4                  // ceil(1014/270)
#define GY    64                 // ceil(1014/16)

#define AB_BYTES (OH * PAB * 16)             // 71936
#define C_OFF    AB_BYTES
#define SMEM_BYTES (C_OFF + OH * PC * 4)     // 90496

typedef unsigned long long ull;

// ---------------- packed f32x2 helpers ----------------
__device__ __forceinline__ ull f2add(ull a, ull b) {
    ull r; asm("add.rn.f32x2 %0, %1, %2;" : "=l"(r) : "l"(a), "l"(b)); return r;
}
__device__ __forceinline__ ull f2fma(ull a, ull b, ull c) {
    ull r; asm("fma.rn.f32x2 %0, %1, %2, %3;" : "=l"(r) : "l"(a), "l"(b), "l"(c)); return r;
}
__device__ __forceinline__ void f2unpack(ull v, float& lo, float& hi) {
    asm("mov.b64 {%0, %1}, %2;" : "=f"(lo), "=f"(hi) : "l"(v));
}
#define F2_NEG1 0xBF800000BF800000ULL
#define F2_SGN  0x8000000080000000ULL

// ---------------- device globals ----------
__device__ unsigned g_min1u, g_max1u, g_min2u, g_max2u;
__device__ double   g_sum;
__device__ float    g_k1, g_b1, g_k2, g_b2, g_u, g_invs, g_thr;

__device__ __forceinline__ unsigned fenc(float f) {
    unsigned b = __float_as_uint(f);
    return (b & 0x80000000u) ? ~b : (b | 0x80000000u);
}
__device__ __forceinline__ float fdec(unsigned u) {
    unsigned b = (u & 0x80000000u) ? (u ^ 0x80000000u) : ~u;
    return __uint_as_float(b);
}

__global__ void init_k() {
    g_min1u = 0xFFFFFFFFu; g_max1u = 0u;
    g_min2u = 0xFFFFFFFFu; g_max2u = 0u;
    g_sum   = 0.0;
}

// ---------------- pass 1: global min/max --------------------
__global__ void minmax_k(const float4* __restrict__ a,
                         const float4* __restrict__ b, int n4) {
    float mn1 =  3.4e38f, mx1 = -3.4e38f;
    float mn2 =  3.4e38f, mx2 = -3.4e38f;
    for (int i = blockIdx.x * blockDim.x + threadIdx.x; i < n4;
         i += gridDim.x * blockDim.x) {
        float4 v = a[i];
        mn1 = fminf(mn1, fminf(fminf(v.x, v.y), fminf(v.z, v.w)));
        mx1 = fmaxf(mx1, fmaxf(fmaxf(v.x, v.y), fmaxf(v.z, v.w)));
        float4 w = b[i];
        mn2 = fminf(mn2, fminf(fminf(w.x, w.y), fminf(w.z, w.w)));
        mx2 = fmaxf(mx2, fmaxf(fmaxf(w.x, w.y), fmaxf(w.z, w.w)));
    }
    #pragma unroll
    for (int o = 16; o; o >>= 1) {
        mn1 = fminf(mn1, __shfl_down_sync(0xffffffffu, mn1, o));
        mx1 = fmaxf(mx1, __shfl_down_sync(0xffffffffu, mx1, o));
        mn2 = fminf(mn2, __shfl_down_sync(0xffffffffu, mn2, o));
        mx2 = fmaxf(mx2, __shfl_down_sync(0xffffffffu, mx2, o));
    }
    __shared__ float s0[8], s1[8], s2[8], s3[8];
    int lane = threadIdx.x & 31, warp = threadIdx.x >> 5;
    if (lane == 0) { s0[warp] = mn1; s1[warp] = mx1; s2[warp] = mn2; s3[warp] = mx2; }
    __syncthreads();
    if (threadIdx.x == 0) {
        for (int w = 1; w < 8; w++) {
            mn1 = fminf(mn1, s0[w]); mx1 = fmaxf(mx1, s1[w]);
            mn2 = fminf(mn2, s2[w]); mx2 = fmaxf(mx2, s3[w]);
        }
        atomicMin(&g_min1u, fenc(mn1)); atomicMax(&g_max1u, fenc(mx1));
        atomicMin(&g_min2u, fenc(mn2)); atomicMax(&g_max2u, fenc(mx2));
    }
}

// ---------------- pass 2: constants ------------
__global__ void prep_k() {
    float mn1 = fdec(g_min1u), mx1 = fdec(g_max1u);
    float mn2 = fdec(g_min2u), mx2 = fdec(g_max2u);
    float k1 = 255.0f / (mx1 - mn1 + 1e-6f);
    float k2 = 255.0f / (mx2 - mn2 + 1e-6f);
    g_k1 = k1; g_b1 = -mn1 * k1;
    g_k2 = k2; g_b2 = -mn2 * k2;
    double csf = 100.0 * 2.6 * (0.0192 + 0.114 * 16.0) * exp(-pow(0.114 * 16.0, 1.1));
    double u   = 128.0 / (1.4 * csf);
    double sg  = u / 3.0;
    g_u    = (float)u;
    g_invs = (float)(1.0 / (sg * sqrt(2.0)));
    double st = u + 4.0 * sg * sqrt(2.0);   // erf arg >= 4 => saturates to 1.0f
    g_thr = (float)(st * st);
}

// exact slow path (out of hot loop; never taken on this data)
__device__ __noinline__ float slow_px(float v1, float v2, float cv,
                                      float U, float IS) {
    float sg1 = sqrtf(fmaxf(v1, 0.0f) + 1e-6f);
    float sg2 = sqrtf(fmaxf(v2, 0.0f) + 1e-6f);
    float pA = 0.5f * (1.0f + erff((sg1 - U) * IS));
    float pB = 0.5f * (1.0f + erff((sg2 - U) * IS));
    float num = 2.0f * pA * pB + 0.01f;
    float den = pA * pA + pB * pB + 0.01f;
    return (num / den) * ((cv + 10.0f) / (sg1 * sg2 + 10.0f));
}

__device__ __forceinline__ float px_val(float v1, float v2, float cv,
                                        float thr, float U, float IS) {
    if (fminf(v1, v2) > thr) {
        float p = (v1 + 1e-6f) * (v2 + 1e-6f);
        float s = p * rsqrtf(p);                 // = sg1*sg2
        return __fdividef(cv + 10.0f, s + 10.0f);
    }
    return slow_px(v1, v2, cv, U, IS);
}

// ---------------- phase 1 vertical pass for one column ----------------
template<bool GUARD>
__device__ __forceinline__ void vcol(const float* __restrict__ q1,
                                     const float* __restrict__ q2,
                                     int rowlim, bool colok,
                                     float k1, float b1, float k2, float b2,
                                     float wgt, int t,
                                     float4* __restrict__ AB,
                                     float*  __restrict__ C) {
    float a1[IHT], a2[IHT];
    #pragma unroll
    for (int rr = 0; rr < IHT; rr++) {
        float v1, v2;
        if (GUARD) {
            bool ok = colok && (rr < rowlim);
            v1 = ok ? __ldg(q1 + rr * IMG_W) : 0.0f;
            v2 = ok ? __ldg(q2 + rr * IMG_W) : 0.0f;
        } else {
            v1 = __ldg(q1 + rr * IMG_W);
            v2 = __ldg(q2 + rr * IMG_W);
        }
        a1[rr] = fmaf(v1, k1, b1);
        a2[rr] = fmaf(v2, k2, b2);
    }
    float s1 = 0.f, s2 = 0.f, s11 = 0.f, s22 = 0.f, s12 = 0.f;
    #pragma unroll
    for (int rr = 0; rr < IHT; rr++) {
        float x1 = a1[rr], x2 = a2[rr];
        s1 += x1; s2 += x2;
        s11 = fmaf(x1, x1, s11);
        s22 = fmaf(x2, x2, s22);
        s12 = fmaf(x1, x2, s12);
        if (rr >= WS - 1) {
            int o = rr - (WS - 1);
            AB[o * PAB + t] = make_float4(s1 * wgt, s2 * wgt, s11 * wgt, s22 * wgt);
            C[o * PC + t]   = s12 * wgt;
            float o1 = a1[o], o2 = a2[o];
            s1 -= o1; s2 -= o2;
            s11 -= o1 * o1; s22 -= o2 * o2; s12 -= o1 * o2;
        }
    }
}

// ---------------- pass 3: fused box-filter + TMQI + reduction ----------
__global__ __launch_bounds__(NTHR, 2)
void tmqi_k(const float* __restrict__ img1, const float* __restrict__ img2) {
    extern __shared__ char sm[];
    float4* AB = (float4*)sm;
    float*  C  = (float*)(sm + C_OFF);

    const int tid = threadIdx.x;
    const int ox0 = blockIdx.x * OWT;
    const int oy0 = blockIdx.y * OH;
    const int bz  = blockIdx.z;
    const bool full = (blockIdx.x < GX - 1) && (blockIdx.y < GY - 1);

    const float k1 = g_k1, b1 = g_b1, k2 = g_k2, b2 = g_b2;
    const float wgt = 1.0f / (float)(WS * WS);
    const float* p1 = img1 + (size_t)bz * IMG_H * IMG_W + (size_t)oy0 * IMG_W + ox0;
    const float* p2 = img2 + (size_t)bz * IMG_H * IMG_W + (size_t)oy0 * IMG_W + ox0;
    const int rowlim = min(IHT, IMG_H - oy0);

    // --- phase 1: one column per thread (threads 280..287 idle) ---
    if (tid < ICT) {
        if (full)
            vcol<false>(p1 + tid, p2 + tid, IHT, true, k1, b1, k2, b2, wgt,
                        tid, AB, C);
        else
            vcol<true>(p1 + tid, p2 + tid, rowlim, ox0 + tid < IMG_W,
                       k1, b1, k2, b2, wgt, tid, AB, C);
    }
    __syncthreads();

    // --- phase 2: rolling horizontal windows + TMQI map ---
    float acc = 0.0f;
    {
        const int r  = tid & 15;
        const int ck = tid >> 4;            // 0..17
        const int x0 = ck * CW;
        const float U = g_u, IS = g_invs, thr = g_thr;
        const bool rowok = full || (oy0 + r < OUT_H);
        const int maxi = OUT_W - (ox0 + x0);  // valid outputs: j < maxi

        const ulonglong2* ABr = (const ulonglong2*)(AB + r * PAB + x0);
        const float*      Cr  = C + r * PC + x0;

        ull rm[WS], rv[WS];
        float rc[WS];
        ull hm = 0ULL, hv = 0ULL;
        float hc = 0.0f;

        #pragma unroll
        for (int j = 0; j < WS - 1; j++) {
            ulonglong2 t = ABr[j];
            float c = Cr[j];
            hm = f2add(hm, t.x); hv = f2add(hv, t.y); hc += c;
            rm[j] = t.x; rv[j] = t.y; rc[j] = c;
        }
        #pragma unroll
        for (int j = 0; j < CW; j++) {
            ulonglong2 t = ABr[j + WS - 1];
            float c = Cr[j + WS - 1];
            hm = f2add(hm, t.x); hv = f2add(hv, t.y); hc += c;

            ull m12 = hm;
            ull v12 = f2fma(m12, m12 ^ F2_SGN, hv);   // s - m*m
            float m1, m2, v1, v2;
            f2unpack(m12, m1, m2);
            f2unpack(v12, v1, v2);
            float cv = fmaf(-m1, m2, hc);
            if (rowok && j < maxi)
                acc += px_val(v1, v2, cv, thr, U, IS);

            // subtract tail (col x0+j), stored in slot j % WS
            hm = f2fma(rm[j % WS], F2_NEG1, hm);
            hv = f2fma(rv[j % WS], F2_NEG1, hv);
            hc -= rc[j % WS];
            // store head (col x0+j+10) in slot (j+10) % WS
            rm[(j + WS - 1) % WS] = t.x;
            rv[(j + WS - 1) % WS] = t.y;
            rc[(j + WS - 1) % WS] = c;
        }
    }

    // --- block reduction (9 warps) ---
    #pragma unroll
    for (int o = 16; o; o >>= 1)
        acc += __shfl_down_sync(0xffffffffu, acc, o);
    __shared__ float red[9];
    if ((tid & 31) == 0) red[tid >> 5] = acc;
    __syncthreads();
    if (tid == 0) {
        float v = red[0];
        #pragma unroll
        for (int i = 1; i < 9; i++) v += red[i];
        atomicAdd(&g_sum, (double)v);
    }
}

__global__ void final_k(float* out) {
    out[0] = (float)(g_sum / ((double)IMG_N * OUT_H * OUT_W));
}

// ---------------- launch -----------------------------------------------
extern "C" void kernel_launch(void* const* d_in, const int* in_sizes, int n_in,
                              void* d_out, int out_size) {
    const float* img1 = (const float*)d_in[0];
    const float* img2 = (const float*)d_in[1];
    float* out = (float*)d_out;

    init_k<<<1, 1>>>();

    int n4 = (IMG_N * IMG_H * IMG_W) / 4;
    minmax_k<<<2048, 256>>>((const float4*)img1, (const float4*)img2, n4);

    prep_k<<<1, 1>>>();

    cudaFuncSetAttribute(tmqi_k, cudaFuncAttributeMaxDynamicSharedMemorySize,
                         SMEM_BYTES);
    dim3 grid(GX, GY, IMG_N);   // (4, 64, 16)
    tmqi_k<<<grid, NTHR, SMEM_BYTES>>>(img1, img2);

    final_k<<<1, 1>>>(out);
}